// round 1
// baseline (speedup 1.0000x reference)
#include <cuda_runtime.h>
#include <cuda_bf16.h>

// DynamicFC: out[b,o,h,w] = sum_i weight[b,o,i] * input[b,i,h,w] + bias[b,o]
// B=64, Cin=Cout=512, H=W=28 (HW=784), fp32.
// Per-batch GEMM: C[512,784] = W[512,512] @ X[512,784] + bias.
//
// Round-1 baseline: register-blocked SGEMM.
//   Tile BM=128, BN=112, BK=16; 256 threads; 8x7 per-thread microtile.
//   512 % 128 == 0, 784 % 112 == 0, 512 % 16 == 0 -> no bounds checks.

#define BM 128
#define BN 112
#define BK 16
#define TM 8
#define TN 7

#define COUT 512
#define CIN  512
#define HW   784

__global__ __launch_bounds__(256, 2)
void dynfc_sgemm_kernel(const float* __restrict__ input,
                        const float* __restrict__ weight,
                        const float* __restrict__ bias,
                        float* __restrict__ out)
{
    const int b  = blockIdx.z;
    const int m0 = blockIdx.y * BM;   // Cout tile
    const int n0 = blockIdx.x * BN;   // HW tile

    const float* Wb = weight + (size_t)b * COUT * CIN;
    const float* Xb = input  + (size_t)b * CIN * HW;
    float*       Cb = out    + (size_t)b * COUT * HW;

    __shared__ float As[BK][BM];   // k-major (transposed) weight tile
    __shared__ float Bs[BK][BN];   // k-major input tile

    const int tid = threadIdx.x;
    const int tx  = tid & 15;      // 0..15 -> n direction
    const int ty  = tid >> 4;      // 0..15 -> m direction

    const int mrow = ty * TM;      // local m base
    const int ncol = tx * TN;      // local n base

    // Init accumulators with bias (each of the 8 rows has its own bias value).
    float acc[TM][TN];
    #pragma unroll
    for (int i = 0; i < TM; i++) {
        const float bv = bias[b * COUT + m0 + mrow + i];
        #pragma unroll
        for (int j = 0; j < TN; j++) acc[i][j] = bv;
    }

    for (int k0 = 0; k0 < CIN; k0 += BK) {
        // --- Load A tile: 128 rows x 16 k, float4-vectorized, store transposed.
        // 512 float4 total, 2 per thread.
        #pragma unroll
        for (int f = 0; f < 2; f++) {
            const int fid = tid + f * 256;       // 0..511
            const int row = fid >> 2;            // 0..127 (m)
            const int kc  = (fid & 3) * 4;       // 0,4,8,12 (k)
            const float4 v = *reinterpret_cast<const float4*>(
                &Wb[(size_t)(m0 + row) * CIN + k0 + kc]);
            As[kc + 0][row] = v.x;
            As[kc + 1][row] = v.y;
            As[kc + 2][row] = v.z;
            As[kc + 3][row] = v.w;
        }
        // --- Load B tile: 16 k-rows x 112 cols. 1792 floats, 7 per thread.
        #pragma unroll
        for (int f = 0; f < 7; f++) {
            const int idx = tid + f * 256;       // 0..1791
            const int row = idx / BN;            // k
            const int col = idx - row * BN;      // n
            Bs[row][col] = Xb[(size_t)(k0 + row) * HW + n0 + col];
        }
        __syncthreads();

        // --- Compute 16 k-steps of the 8x7 microtile.
        #pragma unroll
        for (int k = 0; k < BK; k++) {
            float a[TM];
            #pragma unroll
            for (int i = 0; i < TM; i++) a[i] = As[k][mrow + i];
            float bb[TN];
            #pragma unroll
            for (int j = 0; j < TN; j++) bb[j] = Bs[k][ncol + j];
            #pragma unroll
            for (int i = 0; i < TM; i++)
                #pragma unroll
                for (int j = 0; j < TN; j++)
                    acc[i][j] = fmaf(a[i], bb[j], acc[i][j]);
        }
        __syncthreads();
    }

    // --- Store.
    #pragma unroll
    for (int i = 0; i < TM; i++) {
        float* crow = &Cb[(size_t)(m0 + mrow + i) * HW + n0 + ncol];
        #pragma unroll
        for (int j = 0; j < TN; j++) crow[j] = acc[i][j];
    }
}

extern "C" void kernel_launch(void* const* d_in, const int* in_sizes, int n_in,
                              void* d_out, int out_size)
{
    const float* input  = (const float*)d_in[0];  // (64, 512, 28, 28)
    const float* weight = (const float*)d_in[1];  // (64, 512, 512, 1, 1)
    const float* bias   = (const float*)d_in[2];  // (64, 512)
    float* out = (float*)d_out;                   // (64, 512, 28, 28)

    dim3 grid(HW / BN, COUT / BM, 64);            // (7, 4, 64)
    dim3 block(256);
    dynfc_sgemm_kernel<<<grid, block>>>(input, weight, bias, out);
}

// round 5
// speedup vs baseline: 3.0718x; 3.0718x over previous
#include <cuda_runtime.h>
#include <cstdint>
#include <cstddef>

// DynamicFC: out[b,o,h,w] = sum_i W[b,o,i] * X[b,i,h,w] + bias[b,o]
// B=64, Cin=Cout=512, HW=784, fp32.  Per-batch GEMM C[512,784] = W @ X + bias.
//
// R3: tensor cores via mma.sync.m16n8k8 tf32 (plain sm_80+ PTX — the harness
// targets compute_103 without the 'a' suffix, so tcgen05 is unavailable).
// CTA tile 128x112x32, 256 thr, warp tile 32x56 (2x7 atoms), 4-stage cp.async,
// conflict-free padded SMEM (A stride 36, B stride 120), in-register
// cvt.rna.tf32 rounding of both operands, bias in accumulator init.

#define COUT 512
#define CIN  512
#define HW   784

#define BM 128
#define BN 112
#define BK 32
#define NSTAGES 4
#define NITERS (CIN / BK)     // 16

#define AST 36                // A smem row stride (floats): bank (4g+tg) all distinct
#define BST 120               // B smem row stride (floats): bank (24tg+g) all distinct
#define A_STAGE (BM * AST)    // 4608 floats = 18432 B
#define B_STAGE (BK * BST)    // 3840 floats = 15360 B
#define SMEM_FLOATS (NSTAGES * (A_STAGE + B_STAGE))   // 33792 floats = 135168 B

__device__ __forceinline__ uint32_t smem_u32(const void* p) {
    uint32_t a;
    asm("{ .reg .u64 t; cvta.to.shared.u64 t, %1; cvt.u32.u64 %0, t; }"
        : "=r"(a) : "l"(p));
    return a;
}
__device__ __forceinline__ uint32_t f2tf32(float x) {
    uint32_t u;
    asm("cvt.rna.tf32.f32 %0, %1;" : "=r"(u) : "f"(x));
    return u;
}
__device__ __forceinline__ void cpasync16(uint32_t s, const void* g) {
    asm volatile("cp.async.cg.shared.global [%0], [%1], 16;" :: "r"(s), "l"(g));
}
__device__ __forceinline__ void mma1688(float* c, const uint32_t* a, const uint32_t* b) {
    asm volatile(
        "mma.sync.aligned.m16n8k8.row.col.f32.tf32.tf32.f32 "
        "{%0,%1,%2,%3}, {%4,%5,%6,%7}, {%8,%9}, {%0,%1,%2,%3};"
        : "+f"(c[0]), "+f"(c[1]), "+f"(c[2]), "+f"(c[3])
        : "r"(a[0]), "r"(a[1]), "r"(a[2]), "r"(a[3]), "r"(b[0]), "r"(b[1]));
}

__device__ __forceinline__ void fill_stage(int st, int tid, uint32_t sb,
                                           const float* __restrict__ Wb,
                                           const float* __restrict__ Xb, int n0) {
    const int buf = st & (NSTAGES - 1);
    const uint32_t aB = sb + buf * (A_STAGE * 4);
    const uint32_t bB = sb + NSTAGES * (A_STAGE * 4) + buf * (B_STAGE * 4);
    const int k0 = st * BK;
    // A: 128 rows x 32 k = 1024 float4 chunks (4/thread)
#pragma unroll
    for (int i = 0; i < 4; i++) {
        const int c   = tid + i * 256;
        const int row = c >> 3;         // m
        const int kb  = c & 7;          // k chunk
        cpasync16(aB + (row * AST + kb * 4) * 4,
                  Wb + (size_t)row * CIN + k0 + kb * 4);
    }
    // B: 32 rows x 112 = 896 float4 chunks (3-4/thread)
#pragma unroll
    for (int i = 0; i < 4; i++) {
        const int c = tid + i * 256;
        if (c < 896) {
            const int row = c / 28;
            const int ch  = c - row * 28;
            cpasync16(bB + (row * BST + ch * 4) * 4,
                      Xb + (size_t)(k0 + row) * HW + n0 + ch * 4);
        }
    }
    asm volatile("cp.async.commit_group;" ::: "memory");
}

__global__ __launch_bounds__(256, 1)
void dynfc_tf32_kernel(const float* __restrict__ input,
                       const float* __restrict__ weight,
                       const float* __restrict__ bias,
                       float* __restrict__ out)
{
    extern __shared__ float smem[];
    const uint32_t sb = smem_u32(smem);

    const int tid  = threadIdx.x;
    const int wid  = tid >> 5;
    const int lane = tid & 31;
    const int g    = lane >> 2;      // group id (0..7)
    const int tg   = lane & 3;       // thread-in-group (0..3)
    const int wm   = wid >> 1;       // 0..3  (m warps)
    const int wn   = wid & 1;        // 0..1  (n warps)

    const int b  = blockIdx.z;
    const int m0 = blockIdx.y * BM;
    const int n0 = blockIdx.x * BN;

    const float* Wb = weight + ((size_t)b * COUT + m0) * CIN;
    const float* Xb = input  + (size_t)b * CIN * HW;

    // Accumulators: 2 m-atoms x 7 n-atoms x 4, init with bias per output row.
    float acc[2][7][4];
#pragma unroll
    for (int am = 0; am < 2; am++) {
        const int r0 = m0 + wm * 32 + am * 16 + g;
        const float bv0 = bias[b * COUT + r0];
        const float bv1 = bias[b * COUT + r0 + 8];
#pragma unroll
        for (int j = 0; j < 7; j++) {
            acc[am][j][0] = bv0; acc[am][j][1] = bv0;
            acc[am][j][2] = bv1; acc[am][j][3] = bv1;
        }
    }

    // Prologue: fill stages 0..2
    for (int s = 0; s < NSTAGES - 1; s++) fill_stage(s, tid, sb, Wb, Xb, n0);

    for (int s = 0; s < NITERS; s++) {
        const int buf = s & (NSTAGES - 1);
        if (s < NITERS - 3) {
            asm volatile("cp.async.wait_group 2;" ::: "memory");
        } else {
            asm volatile("cp.async.wait_group 0;" ::: "memory");
        }
        __syncthreads();
        if (s + NSTAGES - 1 < NITERS) fill_stage(s + NSTAGES - 1, tid, sb, Wb, Xb, n0);

        const float* Aw = smem + buf * A_STAGE + (wm * 32) * AST;
        const float* Bw = smem + NSTAGES * A_STAGE + buf * B_STAGE + wn * 56;

#pragma unroll
        for (int ks = 0; ks < BK / 8; ks++) {
            uint32_t afrag[2][4];
#pragma unroll
            for (int am = 0; am < 2; am++) {
                const float* ap = Aw + (am * 16 + g) * AST + ks * 8 + tg;
                afrag[am][0] = f2tf32(ap[0]);
                afrag[am][1] = f2tf32(ap[8 * AST]);
                afrag[am][2] = f2tf32(ap[4]);
                afrag[am][3] = f2tf32(ap[8 * AST + 4]);
            }
            uint32_t bfrag[7][2];
#pragma unroll
            for (int j = 0; j < 7; j++) {
                const float* bp = Bw + (ks * 8 + tg) * BST + j * 8 + g;
                bfrag[j][0] = f2tf32(bp[0]);
                bfrag[j][1] = f2tf32(bp[4 * BST]);
            }
#pragma unroll
            for (int am = 0; am < 2; am++)
#pragma unroll
                for (int j = 0; j < 7; j++)
                    mma1688(acc[am][j], afrag[am], bfrag[j]);
        }
    }

    // Epilogue: direct float2 stores (cols 2tg, 2tg+1 contiguous).
    float* Cb = out + (size_t)b * COUT * HW;
#pragma unroll
    for (int am = 0; am < 2; am++) {
        const int r0 = m0 + wm * 32 + am * 16 + g;
#pragma unroll
        for (int j = 0; j < 7; j++) {
            const int col = n0 + wn * 56 + j * 8 + 2 * tg;
            float2 v0 = make_float2(acc[am][j][0], acc[am][j][1]);
            float2 v1 = make_float2(acc[am][j][2], acc[am][j][3]);
            *reinterpret_cast<float2*>(Cb + (size_t)r0 * HW + col)       = v0;
            *reinterpret_cast<float2*>(Cb + (size_t)(r0 + 8) * HW + col) = v1;
        }
    }
}

extern "C" void kernel_launch(void* const* d_in, const int* in_sizes, int n_in,
                              void* d_out, int out_size)
{
    const float* input  = (const float*)d_in[0];  // (64, 512, 28, 28)
    const float* weight = (const float*)d_in[1];  // (64, 512, 512, 1, 1)
    const float* bias   = (const float*)d_in[2];  // (64, 512)
    float* out = (float*)d_out;

    cudaFuncSetAttribute(dynfc_tf32_kernel,
                         cudaFuncAttributeMaxDynamicSharedMemorySize,
                         SMEM_FLOATS * 4);
    dim3 grid(HW / BN, COUT / BM, 64);            // (7, 4, 64)
    dynfc_tf32_kernel<<<grid, 256, SMEM_FLOATS * 4>>>(input, weight, bias, out);
}

// round 6
// speedup vs baseline: 3.6458x; 1.1869x over previous
#include <cuda_runtime.h>
#include <cstdint>
#include <cstddef>

// DynamicFC: out[b,o,h,w] = sum_i W[b,o,i] * X[b,i,h,w] + bias[b,o]
// B=64, Cin=Cout=512, HW=784, fp32.  Per-batch GEMM C[512,784] = W @ X + bias.
//
// R4: same tf32 mma.sync kernel as R3, but 3-stage pipeline (101KB smem) +
// __launch_bounds__(256,2) so TWO CTAs fit per SM. Occupancy 12.3% -> ~24%,
// covering MMA/LDS latency with warps instead of pipeline depth.

#define COUT 512
#define CIN  512
#define HW   784

#define BM 128
#define BN 112
#define BK 32
#define NSTAGES 3
#define NITERS (CIN / BK)     // 16

#define AST 36                // A smem row stride (floats): conflict-free
#define BST 120               // B smem row stride (floats): conflict-free
#define A_STAGE (BM * AST)    // 4608 floats
#define B_STAGE (BK * BST)    // 3840 floats
#define SMEM_FLOATS (NSTAGES * (A_STAGE + B_STAGE))   // 25344 floats = 101376 B

__device__ __forceinline__ uint32_t smem_u32(const void* p) {
    uint32_t a;
    asm("{ .reg .u64 t; cvta.to.shared.u64 t, %1; cvt.u32.u64 %0, t; }"
        : "=r"(a) : "l"(p));
    return a;
}
__device__ __forceinline__ uint32_t f2tf32(float x) {
    uint32_t u;
    asm("cvt.rna.tf32.f32 %0, %1;" : "=r"(u) : "f"(x));
    return u;
}
__device__ __forceinline__ void cpasync16(uint32_t s, const void* g) {
    asm volatile("cp.async.cg.shared.global [%0], [%1], 16;" :: "r"(s), "l"(g));
}
__device__ __forceinline__ void mma1688(float* c, const uint32_t* a, const uint32_t* b) {
    asm volatile(
        "mma.sync.aligned.m16n8k8.row.col.f32.tf32.tf32.f32 "
        "{%0,%1,%2,%3}, {%4,%5,%6,%7}, {%8,%9}, {%0,%1,%2,%3};"
        : "+f"(c[0]), "+f"(c[1]), "+f"(c[2]), "+f"(c[3])
        : "r"(a[0]), "r"(a[1]), "r"(a[2]), "r"(a[3]), "r"(b[0]), "r"(b[1]));
}

__device__ __forceinline__ void fill_stage(int st, int tid, uint32_t sb,
                                           const float* __restrict__ Wb,
                                           const float* __restrict__ Xb, int n0) {
    const int buf = st % NSTAGES;
    const uint32_t aB = sb + buf * (A_STAGE * 4);
    const uint32_t bB = sb + NSTAGES * (A_STAGE * 4) + buf * (B_STAGE * 4);
    const int k0 = st * BK;
    // A: 128 rows x 32 k = 1024 float4 chunks (4/thread)
#pragma unroll
    for (int i = 0; i < 4; i++) {
        const int c   = tid + i * 256;
        const int row = c >> 3;         // m
        const int kb  = c & 7;          // k chunk
        cpasync16(aB + (row * AST + kb * 4) * 4,
                  Wb + (size_t)row * CIN + k0 + kb * 4);
    }
    // B: 32 rows x 112 cols = 896 float4 chunks
#pragma unroll
    for (int i = 0; i < 4; i++) {
        const int c = tid + i * 256;
        if (c < 896) {
            const int row = c / 28;
            const int ch  = c - row * 28;
            cpasync16(bB + (row * BST + ch * 4) * 4,
                      Xb + (size_t)(k0 + row) * HW + n0 + ch * 4);
        }
    }
    asm volatile("cp.async.commit_group;" ::: "memory");
}

__global__ __launch_bounds__(256, 2)
void dynfc_tf32_kernel(const float* __restrict__ input,
                       const float* __restrict__ weight,
                       const float* __restrict__ bias,
                       float* __restrict__ out)
{
    extern __shared__ float smem[];
    const uint32_t sb = smem_u32(smem);

    const int tid  = threadIdx.x;
    const int wid  = tid >> 5;
    const int lane = tid & 31;
    const int g    = lane >> 2;      // 0..7
    const int tg   = lane & 3;       // 0..3
    const int wm   = wid >> 1;       // 0..3 (m warps)
    const int wn   = wid & 1;        // 0..1 (n warps)

    const int b  = blockIdx.z;
    const int m0 = blockIdx.y * BM;
    const int n0 = blockIdx.x * BN;

    const float* Wb = weight + ((size_t)b * COUT + m0) * CIN;
    const float* Xb = input  + (size_t)b * CIN * HW;

    // Accumulators: 2 m-atoms x 7 n-atoms x 4, bias folded into init.
    float acc[2][7][4];
#pragma unroll
    for (int am = 0; am < 2; am++) {
        const int r0 = m0 + wm * 32 + am * 16 + g;
        const float bv0 = bias[b * COUT + r0];
        const float bv1 = bias[b * COUT + r0 + 8];
#pragma unroll
        for (int j = 0; j < 7; j++) {
            acc[am][j][0] = bv0; acc[am][j][1] = bv0;
            acc[am][j][2] = bv1; acc[am][j][3] = bv1;
        }
    }

    // Prologue: fill stages 0, 1.
    for (int s = 0; s < NSTAGES - 1; s++) fill_stage(s, tid, sb, Wb, Xb, n0);

    for (int s = 0; s < NITERS; s++) {
        const int buf = s % NSTAGES;
        if (s < NITERS - 1) {
            asm volatile("cp.async.wait_group 1;" ::: "memory");
        } else {
            asm volatile("cp.async.wait_group 0;" ::: "memory");
        }
        __syncthreads();
        if (s + NSTAGES - 1 < NITERS) fill_stage(s + NSTAGES - 1, tid, sb, Wb, Xb, n0);

        const float* Aw = smem + buf * A_STAGE + (wm * 32) * AST;
        const float* Bw = smem + NSTAGES * A_STAGE + buf * B_STAGE + wn * 56;

#pragma unroll
        for (int ks = 0; ks < BK / 8; ks++) {
            uint32_t afrag[2][4];
#pragma unroll
            for (int am = 0; am < 2; am++) {
                const float* ap = Aw + (am * 16 + g) * AST + ks * 8 + tg;
                afrag[am][0] = f2tf32(ap[0]);
                afrag[am][1] = f2tf32(ap[8 * AST]);
                afrag[am][2] = f2tf32(ap[4]);
                afrag[am][3] = f2tf32(ap[8 * AST + 4]);
            }
            uint32_t bfrag[7][2];
#pragma unroll
            for (int j = 0; j < 7; j++) {
                const float* bp = Bw + (ks * 8 + tg) * BST + j * 8 + g;
                bfrag[j][0] = f2tf32(bp[0]);
                bfrag[j][1] = f2tf32(bp[4 * BST]);
            }
#pragma unroll
            for (int am = 0; am < 2; am++)
#pragma unroll
                for (int j = 0; j < 7; j++)
                    mma1688(acc[am][j], afrag[am], bfrag[j]);
        }
        __syncthreads();
    }

    // Epilogue: direct float2 stores (cols 2tg, 2tg+1 contiguous).
    float* Cb = out + (size_t)b * COUT * HW;
#pragma unroll
    for (int am = 0; am < 2; am++) {
        const int r0 = m0 + wm * 32 + am * 16 + g;
#pragma unroll
        for (int j = 0; j < 7; j++) {
            const int col = n0 + wn * 56 + j * 8 + 2 * tg;
            float2 v0 = make_float2(acc[am][j][0], acc[am][j][1]);
            float2 v1 = make_float2(acc[am][j][2], acc[am][j][3]);
            *reinterpret_cast<float2*>(Cb + (size_t)r0 * HW + col)       = v0;
            *reinterpret_cast<float2*>(Cb + (size_t)(r0 + 8) * HW + col) = v1;
        }
    }
}

extern "C" void kernel_launch(void* const* d_in, const int* in_sizes, int n_in,
                              void* d_out, int out_size)
{
    const float* input  = (const float*)d_in[0];  // (64, 512, 28, 28)
    const float* weight = (const float*)d_in[1];  // (64, 512, 512, 1, 1)
    const float* bias   = (const float*)d_in[2];  // (64, 512)
    float* out = (float*)d_out;

    cudaFuncSetAttribute(dynfc_tf32_kernel,
                         cudaFuncAttributeMaxDynamicSharedMemorySize,
                         SMEM_FLOATS * 4);
    dim3 grid(HW / BN, COUT / BM, 64);            // (7, 4, 64)
    dynfc_tf32_kernel<<<grid, 256, SMEM_FLOATS * 4>>>(input, weight, bias, out);
}

// round 7
// speedup vs baseline: 3.6773x; 1.0086x over previous
#include <cuda_runtime.h>
#include <cstdint>
#include <cstddef>

// DynamicFC: out[b,o,h,w] = sum_i W[b,o,i] * X[b,i,h,w] + bias[b,o]
// B=64, Cin=Cout=512, HW=784, fp32.  Per-batch GEMM C[512,784] = W @ X + bias.
//
// R5: tf32 mma.sync kernel; B operand is rounded to tf32 AT FILL TIME
// (LDG.128 -> cvt.rna x4 -> STS.128) so the inner loop loads raw bits for B
// (no cvt on the LDS->MMA critical path). A stays cp.async + in-register cvt.
// 2 smem buffers, register-staged B prefetch, ONE __syncthreads per K-stage.

#define COUT 512
#define CIN  512
#define HW   784

#define BM 128
#define BN 112
#define BK 32
#define NITERS (CIN / BK)     // 16

#define AST 36                // A smem row stride (floats): conflict-free LDS
#define BST 120               // B smem row stride (floats): conflict-free LDS
#define A_STAGE (BM * AST)    // 4608 floats
#define B_STAGE (BK * BST)    // 3840 floats
#define SMEM_FLOATS (2 * (A_STAGE + B_STAGE))   // 16896 floats = 67584 B

__device__ __forceinline__ uint32_t smem_u32(const void* p) {
    uint32_t a;
    asm("{ .reg .u64 t; cvta.to.shared.u64 t, %1; cvt.u32.u64 %0, t; }"
        : "=r"(a) : "l"(p));
    return a;
}
__device__ __forceinline__ uint32_t f2tf32(float x) {
    uint32_t u;
    asm("cvt.rna.tf32.f32 %0, %1;" : "=r"(u) : "f"(x));
    return u;
}
__device__ __forceinline__ void cpasync16(uint32_t s, const void* g) {
    asm volatile("cp.async.cg.shared.global [%0], [%1], 16;" :: "r"(s), "l"(g));
}
__device__ __forceinline__ void mma1688(float* c, const uint32_t* a, const uint32_t* b) {
    asm volatile(
        "mma.sync.aligned.m16n8k8.row.col.f32.tf32.tf32.f32 "
        "{%0,%1,%2,%3}, {%4,%5,%6,%7}, {%8,%9}, {%0,%1,%2,%3};"
        : "+f"(c[0]), "+f"(c[1]), "+f"(c[2]), "+f"(c[3])
        : "r"(a[0]), "r"(a[1]), "r"(a[2]), "r"(a[3]), "r"(b[0]), "r"(b[1]));
}

// ---- A fill: cp.async, 128 rows x 32 k = 1024 float4 chunks (4/thread) ----
__device__ __forceinline__ void fillA_async(int st, int tid, uint32_t sb,
                                            const float* __restrict__ Wb) {
    const uint32_t aB = sb + (st & 1) * (A_STAGE * 4);
    const int k0 = st * BK;
#pragma unroll
    for (int i = 0; i < 4; i++) {
        const int c   = tid + i * 256;
        const int row = c >> 3;
        const int kb  = c & 7;
        cpasync16(aB + (row * AST + kb * 4) * 4,
                  Wb + (size_t)row * CIN + k0 + kb * 4);
    }
    asm volatile("cp.async.commit_group;" ::: "memory");
}

// ---- B fill: LDG.128 staging (3-4 chunks/thread), cvt+STS.128 later -------
__device__ __forceinline__ void ldgB(int st, int tid, float4* r,
                                     const float* __restrict__ Xb, int n0) {
    const int k0 = st * BK;
#pragma unroll
    for (int i = 0; i < 4; i++) {
        const int q = tid + i * 256;
        if (q < 896) {
            const int k  = q / 28;
            const int ch = q - k * 28;
            r[i] = *reinterpret_cast<const float4*>(
                Xb + (size_t)(k0 + k) * HW + n0 + ch * 4);
        }
    }
}
__device__ __forceinline__ void stsB(int st, int tid, uint32_t sb, const float4* r) {
    const uint32_t bB = sb + 2 * (A_STAGE * 4) + (st & 1) * (B_STAGE * 4);
#pragma unroll
    for (int i = 0; i < 4; i++) {
        const int q = tid + i * 256;
        if (q < 896) {
            const int k  = q / 28;
            const int ch = q - k * 28;
            uint4 v;
            v.x = f2tf32(r[i].x); v.y = f2tf32(r[i].y);
            v.z = f2tf32(r[i].z); v.w = f2tf32(r[i].w);
            asm volatile("st.shared.v4.b32 [%0], {%1,%2,%3,%4};"
                         :: "r"(bB + (k * BST + ch * 4) * 4),
                            "r"(v.x), "r"(v.y), "r"(v.z), "r"(v.w) : "memory");
        }
    }
}

__global__ __launch_bounds__(256, 2)
void dynfc_tf32_kernel(const float* __restrict__ input,
                       const float* __restrict__ weight,
                       const float* __restrict__ bias,
                       float* __restrict__ out)
{
    extern __shared__ float smem[];
    const uint32_t sb = smem_u32(smem);

    const int tid  = threadIdx.x;
    const int wid  = tid >> 5;
    const int lane = tid & 31;
    const int g    = lane >> 2;      // 0..7
    const int tg   = lane & 3;       // 0..3
    const int wm   = wid >> 1;       // 0..3 (m warps)
    const int wn   = wid & 1;        // 0..1 (n warps)

    const int b  = blockIdx.z;
    const int m0 = blockIdx.y * BM;
    const int n0 = blockIdx.x * BN;

    const float* Wb = weight + ((size_t)b * COUT + m0) * CIN;
    const float* Xb = input  + (size_t)b * CIN * HW;

    // Accumulators: 2 m-atoms x 7 n-atoms x 4, bias folded into init.
    float acc[2][7][4];
#pragma unroll
    for (int am = 0; am < 2; am++) {
        const int r0 = m0 + wm * 32 + am * 16 + g;
        const float bv0 = bias[b * COUT + r0];
        const float bv1 = bias[b * COUT + r0 + 8];
#pragma unroll
        for (int j = 0; j < 7; j++) {
            acc[am][j][0] = bv0; acc[am][j][1] = bv0;
            acc[am][j][2] = bv1; acc[am][j][3] = bv1;
        }
    }

    float4 rB[4];

    // Prologue: A stages 0,1 async; B stage 0 via regs->smem; B stage 1 staged.
    fillA_async(0, tid, sb, Wb);
    fillA_async(1, tid, sb, Wb);
    ldgB(0, tid, rB, Xb, n0);
    stsB(0, tid, sb, rB);
    ldgB(1, tid, rB, Xb, n0);
    asm volatile("cp.async.wait_group 0;" ::: "memory");
    __syncthreads();

    for (int s = 0; s < NITERS; s++) {
        const int buf = s & 1;
        const float* Aw = smem + buf * A_STAGE + (wm * 32) * AST;
        const float* Bw = smem + 2 * A_STAGE + buf * B_STAGE + wn * 56;

#pragma unroll
        for (int ks = 0; ks < BK / 8; ks++) {
            uint32_t afrag[2][4];
#pragma unroll
            for (int am = 0; am < 2; am++) {
                const float* ap = Aw + (am * 16 + g) * AST + ks * 8 + tg;
                afrag[am][0] = f2tf32(ap[0]);
                afrag[am][1] = f2tf32(ap[8 * AST]);
                afrag[am][2] = f2tf32(ap[4]);
                afrag[am][3] = f2tf32(ap[8 * AST + 4]);
            }
            uint32_t bfrag[7][2];
#pragma unroll
            for (int j = 0; j < 7; j++) {
                const float* bp = Bw + (ks * 8 + tg) * BST + j * 8 + g;
                bfrag[j][0] = __float_as_uint(bp[0]);          // pre-rounded
                bfrag[j][1] = __float_as_uint(bp[4 * BST]);
            }
#pragma unroll
            for (int am = 0; am < 2; am++)
#pragma unroll
                for (int j = 0; j < 7; j++)
                    mma1688(acc[am][j], afrag[am], bfrag[j]);
        }

        // Stage B(s+1) into the other buffer (nobody reads it this stage).
        if (s + 1 < NITERS) stsB(s + 1, tid, sb, rB);
        // A(s+1) must be fully landed (all warps) before next compute.
        asm volatile("cp.async.wait_group 0;" ::: "memory");
        __syncthreads();
        if (s + 2 < NITERS) {
            fillA_async(s + 2, tid, sb, Wb);   // overwrites buf s&1 (safe now)
            ldgB(s + 2, tid, rB, Xb, n0);
        }
    }

    // Epilogue: direct float2 stores (cols 2tg, 2tg+1 contiguous).
    float* Cb = out + (size_t)b * COUT * HW;
#pragma unroll
    for (int am = 0; am < 2; am++) {
        const int r0 = m0 + wm * 32 + am * 16 + g;
#pragma unroll
        for (int j = 0; j < 7; j++) {
            const int col = n0 + wn * 56 + j * 8 + 2 * tg;
            float2 v0 = make_float2(acc[am][j][0], acc[am][j][1]);
            float2 v1 = make_float2(acc[am][j][2], acc[am][j][3]);
            *reinterpret_cast<float2*>(Cb + (size_t)r0 * HW + col)       = v0;
            *reinterpret_cast<float2*>(Cb + (size_t)(r0 + 8) * HW + col) = v1;
        }
    }
}

extern "C" void kernel_launch(void* const* d_in, const int* in_sizes, int n_in,
                              void* d_out, int out_size)
{
    const float* input  = (const float*)d_in[0];  // (64, 512, 28, 28)
    const float* weight = (const float*)d_in[1];  // (64, 512, 512, 1, 1)
    const float* bias   = (const float*)d_in[2];  // (64, 512)
    float* out = (float*)d_out;

    cudaFuncSetAttribute(dynfc_tf32_kernel,
                         cudaFuncAttributeMaxDynamicSharedMemorySize,
                         SMEM_FLOATS * 4);
    dim3 grid(HW / BN, COUT / BM, 64);            // (7, 4, 64)
    dynfc_tf32_kernel<<<grid, 256, SMEM_FLOATS * 4>>>(input, weight, bias, out);
}